// round 2
// baseline (speedup 1.0000x reference)
#include <cuda_runtime.h>

#define N_STATE 256
#define SEQLEN  1024
#define BATCH   64

// ---------------------------------------------------------------------------
// Scan kernel: 32 CTAs, each owns 2 batch lanes for the full 1024-step scan.
// c lives in SMEM (ping-pong), A_t rows streamed from gmem (L1-cached, each
// CTA reads its own copy; 2 batches amortize the 256KB/step A traffic against
// the 131k FMA/step compute).
// ---------------------------------------------------------------------------
__global__ void __launch_bounds__(256) hippo_scan_kernel(
    const float* __restrict__ inputs,   // [64, 1024]
    const float* __restrict__ A_stack,  // [1024, 256, 256] row-major (t, i, j)
    const float* __restrict__ B_stack,  // [1024, 256]
    float* __restrict__ cs)             // [64, 1024, 256]
{
    __shared__ float cbuf[2][2][N_STATE];  // [pingpong][local batch][state]

    const int n  = threadIdx.x;            // state row this thread owns
    const int b0 = blockIdx.x * 2;         // first of two batch lanes

    cbuf[0][0][n] = 0.0f;
    cbuf[0][1][n] = 0.0f;
    __syncthreads();

    int p = 0;
    for (int t = 0; t < SEQLEN; ++t) {
        const float4* __restrict__ Arow = reinterpret_cast<const float4*>(
            A_stack + (size_t)t * (N_STATE * N_STATE) + (size_t)n * N_STATE);
        const float4* c0 = reinterpret_cast<const float4*>(cbuf[p][0]);
        const float4* c1 = reinterpret_cast<const float4*>(cbuf[p][1]);

        // 8 independent accumulator chains for ILP
        float a0x = 0.f, a0y = 0.f, a0z = 0.f, a0w = 0.f;
        float a1x = 0.f, a1y = 0.f, a1z = 0.f, a1w = 0.f;

        #pragma unroll 8
        for (int j = 0; j < N_STATE / 4; ++j) {
            float4 a  = __ldg(&Arow[j]);
            float4 x0 = c0[j];
            float4 x1 = c1[j];
            a0x = fmaf(a.x, x0.x, a0x);
            a0y = fmaf(a.y, x0.y, a0y);
            a0z = fmaf(a.z, x0.z, a0z);
            a0w = fmaf(a.w, x0.w, a0w);
            a1x = fmaf(a.x, x1.x, a1x);
            a1y = fmaf(a.y, x1.y, a1y);
            a1z = fmaf(a.z, x1.z, a1z);
            a1w = fmaf(a.w, x1.w, a1w);
        }
        float acc0 = (a0x + a0y) + (a0z + a0w);
        float acc1 = (a1x + a1y) + (a1z + a1w);

        float bt = B_stack[t * N_STATE + n];
        float f0 = __ldg(&inputs[(size_t)(b0 + 0) * SEQLEN + t]);
        float f1 = __ldg(&inputs[(size_t)(b0 + 1) * SEQLEN + t]);

        float nc0 = fmaf(bt, f0, acc0);
        float nc1 = fmaf(bt, f1, acc1);

        cbuf[p ^ 1][0][n] = nc0;
        cbuf[p ^ 1][1][n] = nc1;

        cs[((size_t)(b0 + 0) * SEQLEN + t) * N_STATE + n] = nc0;
        cs[((size_t)(b0 + 1) * SEQLEN + t) * N_STATE + n] = nc1;

        __syncthreads();   // one barrier per step (ping-pong makes this safe)
        p ^= 1;
    }
}

// ---------------------------------------------------------------------------
// Recon kernel: O[r, m] = sum_n X[r, n] * W[m, n]
//   X = cs viewed as (65536, 256), W = eval_mat (1024, 256), O = (65536, 1024)
// Classic fp32 SGEMM: 128x64 CTA tile, BK=16, 256 threads, 8x4 microtile.
// ---------------------------------------------------------------------------
#define BM 128
#define BN 64
#define BK 16
#define AS_LD 136   // padded leading dim (keeps 16B alignment, breaks bank hits)
#define BS_LD 72

__global__ void __launch_bounds__(256) hippo_recon_kernel(
    const float* __restrict__ X,   // [65536, 256]
    const float* __restrict__ W,   // [1024, 256]
    float* __restrict__ O)         // [65536, 1024]
{
    __shared__ float As[BK][AS_LD];
    __shared__ float Bs[BK][BS_LD];

    const int    tid  = threadIdx.x;
    const size_t row0 = (size_t)blockIdx.x * BM;
    const int    col0 = blockIdx.y * BN;

    const int tm0 = (tid >> 4) * 8;   // 16 groups of 8 rows
    const int tn0 = (tid & 15) * 4;   // 16 groups of 4 cols

    float acc[8][4];
    #pragma unroll
    for (int i = 0; i < 8; ++i)
        #pragma unroll
        for (int j = 0; j < 4; ++j) acc[i][j] = 0.0f;

    for (int k0 = 0; k0 < N_STATE; k0 += BK) {
        // Load X tile: 128 rows x 16 k  (512 float4, 2 per thread), transpose to As[k][row]
        #pragma unroll
        for (int i = 0; i < 2; ++i) {
            int q  = tid + i * 256;
            int r  = q >> 2;
            int c4 = (q & 3) << 2;
            float4 v = *reinterpret_cast<const float4*>(
                X + (row0 + r) * N_STATE + k0 + c4);
            As[c4 + 0][r] = v.x;
            As[c4 + 1][r] = v.y;
            As[c4 + 2][r] = v.z;
            As[c4 + 3][r] = v.w;
        }
        // Load W tile: 64 rows x 16 k (256 float4, 1 per thread), transpose to Bs[k][row]
        {
            int r  = tid >> 2;
            int c4 = (tid & 3) << 2;
            float4 v = *reinterpret_cast<const float4*>(
                W + (size_t)(col0 + r) * N_STATE + k0 + c4);
            Bs[c4 + 0][r] = v.x;
            Bs[c4 + 1][r] = v.y;
            Bs[c4 + 2][r] = v.z;
            Bs[c4 + 3][r] = v.w;
        }
        __syncthreads();

        #pragma unroll
        for (int k = 0; k < BK; ++k) {
            float4 am0 = *reinterpret_cast<const float4*>(&As[k][tm0]);
            float4 am1 = *reinterpret_cast<const float4*>(&As[k][tm0 + 4]);
            float4 bn  = *reinterpret_cast<const float4*>(&Bs[k][tn0]);
            float am[8] = {am0.x, am0.y, am0.z, am0.w, am1.x, am1.y, am1.z, am1.w};
            float bv[4] = {bn.x, bn.y, bn.z, bn.w};
            #pragma unroll
            for (int i = 0; i < 8; ++i)
                #pragma unroll
                for (int j = 0; j < 4; ++j)
                    acc[i][j] = fmaf(am[i], bv[j], acc[i][j]);
        }
        __syncthreads();
    }

    #pragma unroll
    for (int i = 0; i < 8; ++i) {
        size_t r = row0 + tm0 + i;
        float4 v = make_float4(acc[i][0], acc[i][1], acc[i][2], acc[i][3]);
        *reinterpret_cast<float4*>(O + r * 1024 + col0 + tn0) = v;
    }
}

// ---------------------------------------------------------------------------
// kernel_launch: scan -> recon (same stream, graph-capturable, no allocs)
// ---------------------------------------------------------------------------
extern "C" void kernel_launch(void* const* d_in, const int* in_sizes, int n_in,
                              void* d_out, int out_size)
{
    const float* inputs   = (const float*)d_in[0];
    const float* A_stack  = (const float*)d_in[1];
    const float* B_stack  = (const float*)d_in[2];
    const float* eval_mat = (const float*)d_in[3];

    float* out   = (float*)d_out;
    float* cs    = out;                                         // 64*1024*256
    float* recon = out + (size_t)BATCH * SEQLEN * N_STATE;      // 64*1024*1024

    // Phase 1: sequential scan (32 CTAs x 2 batches)
    hippo_scan_kernel<<<BATCH / 2, 256>>>(inputs, A_stack, B_stack, cs);

    // Phase 2: recon GEMM over the full (65536 x 256) cs matrix
    dim3 grid((BATCH * SEQLEN) / BM, 1024 / BN);
    hippo_recon_kernel<<<grid, 256>>>(cs, eval_mat, recon);
}

// round 3
// speedup vs baseline: 1.3949x; 1.3949x over previous
#include <cuda_runtime.h>
#include <cstdint>

#define N_STATE 256
#define SEQLEN  1024
#define BATCH   64

// ---------------------------------------------------------------------------
// helpers
// ---------------------------------------------------------------------------
__device__ __forceinline__ uint32_t smem_u32(const void* p) {
    uint32_t a;
    asm("{ .reg .u64 t; cvta.to.shared.u64 t, %1; cvt.u32.u64 %0, t; }"
        : "=r"(a) : "l"(p));
    return a;
}

// ---------------------------------------------------------------------------
// Scan kernel: 64 CTAs as 32 clusters of 2. Each cluster owns 2 batch lanes;
// each CTA computes 128 of the 256 states. Coalesced A loads:
//   warp owns 16 rows; lanes split (g=lane/8 -> row within quad,
//   k=lane%8 -> 32-element column slice). Each LDG.128 covers 4 contiguous
//   128B lines (4 wavefronts, optimal). 8-lane shfl.bfly reduction per row.
// New state halves exchanged via DSMEM + barrier.cluster each step.
// ---------------------------------------------------------------------------
__global__ void __launch_bounds__(256) __cluster_dims__(2, 1, 1)
hippo_scan_kernel(
    const float* __restrict__ inputs,   // [64, 1024]
    const float* __restrict__ A_stack,  // [1024, 256, 256]
    const float* __restrict__ B_stack,  // [1024, 256]
    float* __restrict__ cs)             // [64, 1024, 256]
{
    __shared__ float cbuf[2][2][N_STATE];   // [parity][batch][state]

    const int tid  = threadIdx.x;
    const int warp = tid >> 5;
    const int lane = tid & 31;
    const int g    = lane >> 3;   // 0..3 : row within quad
    const int k    = lane & 7;    // 0..7 : 32-wide column slice

    uint32_t rank;
    asm("mov.u32 %0, %%cluster_ctarank;" : "=r"(rank));

    const int pair = blockIdx.x >> 1;        // cluster id
    const int b0   = pair * 2;               // two batch lanes per cluster
    const int row0 = (int)rank * 128 + warp * 16;

    // zero initial state (both CTAs init full vector locally)
    cbuf[0][0][tid] = 0.0f;
    cbuf[0][1][tid] = 0.0f;

    const uint32_t my_base = smem_u32(&cbuf[0][0][0]);
    uint32_t peer_base;
    asm("mapa.shared::cluster.u32 %0, %1, %2;"
        : "=r"(peer_base) : "r"(my_base), "r"(rank ^ 1u));

    asm volatile("barrier.cluster.arrive.aligned;" ::: "memory");
    asm volatile("barrier.cluster.wait.aligned;"   ::: "memory");

    int p = 0;
    for (int t = 0; t < SEQLEN; ++t) {
        const float f0 = __ldg(&inputs[(size_t)(b0 + 0) * SEQLEN + t]);
        const float f1 = __ldg(&inputs[(size_t)(b0 + 1) * SEQLEN + t]);

        // load this lane's 32-wide c slice for both batches into registers
        float4 cA[8], cB[8];
        {
            const float4* c0p = reinterpret_cast<const float4*>(&cbuf[p][0][k * 32]);
            const float4* c1p = reinterpret_cast<const float4*>(&cbuf[p][1][k * 32]);
            #pragma unroll
            for (int i = 0; i < 8; ++i) { cA[i] = c0p[i]; cB[i] = c1p[i]; }
        }

        const float* At = A_stack + (size_t)t * (N_STATE * N_STATE);
        const int q = p ^ 1;

        #pragma unroll
        for (int it = 0; it < 4; ++it) {
            const int row = row0 + it * 4 + g;
            const float4* Ar = reinterpret_cast<const float4*>(
                At + (size_t)row * N_STATE + k * 32);

            float s0 = 0.0f, s1 = 0.0f;
            #pragma unroll
            for (int i = 0; i < 8; ++i) {
                float4 a = __ldg(&Ar[i]);
                s0 = fmaf(a.x, cA[i].x, s0);
                s0 = fmaf(a.y, cA[i].y, s0);
                s0 = fmaf(a.z, cA[i].z, s0);
                s0 = fmaf(a.w, cA[i].w, s0);
                s1 = fmaf(a.x, cB[i].x, s1);
                s1 = fmaf(a.y, cB[i].y, s1);
                s1 = fmaf(a.z, cB[i].z, s1);
                s1 = fmaf(a.w, cB[i].w, s1);
            }
            // reduce over the 8 k-lanes (butterfly stays within 8-lane group)
            s0 += __shfl_xor_sync(0xffffffffu, s0, 1);
            s0 += __shfl_xor_sync(0xffffffffu, s0, 2);
            s0 += __shfl_xor_sync(0xffffffffu, s0, 4);
            s1 += __shfl_xor_sync(0xffffffffu, s1, 1);
            s1 += __shfl_xor_sync(0xffffffffu, s1, 2);
            s1 += __shfl_xor_sync(0xffffffffu, s1, 4);

            if (k == 0) {
                const float bt = __ldg(&B_stack[t * N_STATE + row]);
                const float n0 = fmaf(bt, f0, s0);
                const float n1 = fmaf(bt, f1, s1);

                // local half
                cbuf[q][0][row] = n0;
                cbuf[q][1][row] = n1;

                // peer half via DSMEM (ordered by barrier.cluster release/acquire)
                const uint32_t off0 = (uint32_t)((q * 2 + 0) * N_STATE + row) * 4u;
                const uint32_t off1 = off0 + (uint32_t)(N_STATE * 4);
                asm volatile("st.shared::cluster.f32 [%0], %1;"
                             :: "r"(peer_base + off0), "f"(n0) : "memory");
                asm volatile("st.shared::cluster.f32 [%0], %1;"
                             :: "r"(peer_base + off1), "f"(n1) : "memory");

                // global output
                cs[((size_t)(b0 + 0) * SEQLEN + t) * N_STATE + row] = n0;
                cs[((size_t)(b0 + 1) * SEQLEN + t) * N_STATE + row] = n1;
            }
        }

        asm volatile("barrier.cluster.arrive.aligned;" ::: "memory");
        asm volatile("barrier.cluster.wait.aligned;"   ::: "memory");
        p ^= 1;
    }
}

// ---------------------------------------------------------------------------
// Recon kernel: O[r, m] = sum_n X[r, n] * W[m, n]
//   X = (65536, 256) row-major, W = (1024, 256) row-major, O = (65536, 1024)
// 128x128 CTA tile, BK=16, 256 threads, 8x8 microtile.
// ---------------------------------------------------------------------------
#define RBM 128
#define RBN 128
#define RBK 16
#define RLD (RBM + 4)   // 132 floats = 528B rows, keeps 16B alignment

__global__ void __launch_bounds__(256) hippo_recon_kernel(
    const float* __restrict__ X,   // [65536, 256]
    const float* __restrict__ W,   // [1024, 256]
    float* __restrict__ O)         // [65536, 1024]
{
    __shared__ float As[RBK][RLD];
    __shared__ float Bs[RBK][RLD];

    const int    tid  = threadIdx.x;
    const size_t row0 = (size_t)blockIdx.x * RBM;
    const int    col0 = blockIdx.y * RBN;

    const int tx  = tid & 15;
    const int ty  = tid >> 4;
    const int tm0 = ty * 8;
    const int tn0 = tx * 8;

    float acc[8][8];
    #pragma unroll
    for (int i = 0; i < 8; ++i)
        #pragma unroll
        for (int j = 0; j < 8; ++j) acc[i][j] = 0.0f;

    for (int k0 = 0; k0 < N_STATE; k0 += RBK) {
        // load 128x16 tiles of X and W, transposed into As[k][m] / Bs[k][n]
        #pragma unroll
        for (int i = 0; i < 2; ++i) {
            const int q  = tid + i * 256;
            const int r  = q >> 2;
            const int c4 = (q & 3) << 2;
            float4 v = *reinterpret_cast<const float4*>(
                X + (row0 + r) * N_STATE + k0 + c4);
            As[c4 + 0][r] = v.x;
            As[c4 + 1][r] = v.y;
            As[c4 + 2][r] = v.z;
            As[c4 + 3][r] = v.w;
            float4 w = *reinterpret_cast<const float4*>(
                W + (size_t)(col0 + r) * N_STATE + k0 + c4);
            Bs[c4 + 0][r] = w.x;
            Bs[c4 + 1][r] = w.y;
            Bs[c4 + 2][r] = w.z;
            Bs[c4 + 3][r] = w.w;
        }
        __syncthreads();

        #pragma unroll
        for (int kk = 0; kk < RBK; ++kk) {
            float4 a0 = *reinterpret_cast<const float4*>(&As[kk][tm0]);
            float4 a1 = *reinterpret_cast<const float4*>(&As[kk][tm0 + 4]);
            float4 b0 = *reinterpret_cast<const float4*>(&Bs[kk][tn0]);
            float4 b1 = *reinterpret_cast<const float4*>(&Bs[kk][tn0 + 4]);
            float am[8] = {a0.x, a0.y, a0.z, a0.w, a1.x, a1.y, a1.z, a1.w};
            float bn[8] = {b0.x, b0.y, b0.z, b0.w, b1.x, b1.y, b1.z, b1.w};
            #pragma unroll
            for (int i = 0; i < 8; ++i)
                #pragma unroll
                for (int j = 0; j < 8; ++j)
                    acc[i][j] = fmaf(am[i], bn[j], acc[i][j]);
        }
        __syncthreads();
    }

    #pragma unroll
    for (int i = 0; i < 8; ++i) {
        const size_t r = row0 + tm0 + i;
        float4 v0 = make_float4(acc[i][0], acc[i][1], acc[i][2], acc[i][3]);
        float4 v1 = make_float4(acc[i][4], acc[i][5], acc[i][6], acc[i][7]);
        *reinterpret_cast<float4*>(O + r * 1024 + col0 + tn0)     = v0;
        *reinterpret_cast<float4*>(O + r * 1024 + col0 + tn0 + 4) = v1;
    }
}

// ---------------------------------------------------------------------------
// kernel_launch
// ---------------------------------------------------------------------------
extern "C" void kernel_launch(void* const* d_in, const int* in_sizes, int n_in,
                              void* d_out, int out_size)
{
    const float* inputs   = (const float*)d_in[0];
    const float* A_stack  = (const float*)d_in[1];
    const float* B_stack  = (const float*)d_in[2];
    const float* eval_mat = (const float*)d_in[3];

    float* out   = (float*)d_out;
    float* cs    = out;                                      // 64*1024*256
    float* recon = out + (size_t)BATCH * SEQLEN * N_STATE;   // 64*1024*1024

    // Phase 1: sequential scan, 32 clusters of 2 CTAs (64 SMs busy)
    hippo_scan_kernel<<<BATCH, 256>>>(inputs, A_stack, B_stack, cs);

    // Phase 2: recon GEMM (65536 x 1024 x 256)
    dim3 grid((BATCH * SEQLEN) / RBM, 1024 / RBN);
    hippo_recon_kernel<<<grid, 256>>>(cs, eval_mat, recon);
}

// round 4
// speedup vs baseline: 1.7693x; 1.2684x over previous
#include <cuda_runtime.h>
#include <cstdint>

#define N_STATE 256
#define SEQLEN  1024
#define BATCH   64

// ---------------------------------------------------------------------------
// helpers
// ---------------------------------------------------------------------------
__device__ __forceinline__ uint32_t smem_u32(const void* p) {
    uint32_t a;
    asm("{ .reg .u64 t; cvta.to.shared.u64 t, %1; cvt.u32.u64 %0, t; }"
        : "=r"(a) : "l"(p));
    return a;
}

// ---------------------------------------------------------------------------
// Scan kernel: 64 CTAs as 32 clusters of 2. Each cluster owns 2 batch lanes;
// each CTA computes 128 of the 256 states.
//
// PROPERLY coalesced A loads this time:
//   warp owns 16 rows, processed as 4 quads. Lane = (g,k), g=lane>>3 picks the
//   row within the quad, k=lane&7 picks a 16B chunk. Address:
//       row*1024B + i*128B + k*16B     (i = 0..7)
//   -> within one LDG.128, the 8 k-lanes of a row-group cover ONE contiguous
//      128B line; 4 row-groups -> 4 wavefronts/instruction (vs 32 before).
// Per-row partials reduced over the 8 k-lanes with 3 shfl.bfly.
// New state halves exchanged via DSMEM + barrier.cluster each step.
// ---------------------------------------------------------------------------
__global__ void __launch_bounds__(256) __cluster_dims__(2, 1, 1)
hippo_scan_kernel(
    const float* __restrict__ inputs,   // [64, 1024]
    const float* __restrict__ A_stack,  // [1024, 256, 256]
    const float* __restrict__ B_stack,  // [1024, 256]
    float* __restrict__ cs)             // [64, 1024, 256]
{
    __shared__ float cbuf[2][2][N_STATE];   // [parity][batch][state]

    const int tid  = threadIdx.x;
    const int warp = tid >> 5;
    const int lane = tid & 31;
    const int g    = lane >> 3;   // 0..3 : row within quad
    const int k    = lane & 7;    // 0..7 : 16B chunk within a 128B line

    uint32_t rank;
    asm("mov.u32 %0, %%cluster_ctarank;" : "=r"(rank));

    const int pair = blockIdx.x >> 1;        // cluster id
    const int b0   = pair * 2;               // two batch lanes per cluster
    const int row0 = (int)rank * 128 + warp * 16;

    cbuf[0][0][tid] = 0.0f;
    cbuf[0][1][tid] = 0.0f;

    const uint32_t my_base = smem_u32(&cbuf[0][0][0]);
    uint32_t peer_base;
    asm("mapa.shared::cluster.u32 %0, %1, %2;"
        : "=r"(peer_base) : "r"(my_base), "r"(rank ^ 1u));

    asm volatile("barrier.cluster.arrive.aligned;" ::: "memory");
    asm volatile("barrier.cluster.wait.aligned;"   ::: "memory");

    int p = 0;
    for (int t = 0; t < SEQLEN; ++t) {
        const float f0 = __ldg(&inputs[(size_t)(b0 + 0) * SEQLEN + t]);
        const float f1 = __ldg(&inputs[(size_t)(b0 + 1) * SEQLEN + t]);

        // c values this lane needs: cols [i*32 + k*4, +4) for i = 0..7
        // (bank-conflict-free: 8 distinct 16B addrs, broadcast across g groups)
        float4 cA[8], cB[8];
        #pragma unroll
        for (int i = 0; i < 8; ++i) {
            cA[i] = *reinterpret_cast<const float4*>(&cbuf[p][0][i * 32 + k * 4]);
            cB[i] = *reinterpret_cast<const float4*>(&cbuf[p][1][i * 32 + k * 4]);
        }

        const float* At = A_stack + (size_t)t * (N_STATE * N_STATE);
        const int q = p ^ 1;

        #pragma unroll
        for (int it = 0; it < 4; ++it) {
            const int row = row0 + it * 4 + g;
            const float* Arow = At + (size_t)row * N_STATE;

            float s0 = 0.0f, s1 = 0.0f;
            #pragma unroll
            for (int i = 0; i < 8; ++i) {
                // addr = row*1024 + i*128 + k*16  -> coalesced per row-group
                float4 a = __ldg(reinterpret_cast<const float4*>(
                    Arow + i * 32 + k * 4));
                s0 = fmaf(a.x, cA[i].x, s0);
                s0 = fmaf(a.y, cA[i].y, s0);
                s0 = fmaf(a.z, cA[i].z, s0);
                s0 = fmaf(a.w, cA[i].w, s0);
                s1 = fmaf(a.x, cB[i].x, s1);
                s1 = fmaf(a.y, cB[i].y, s1);
                s1 = fmaf(a.z, cB[i].z, s1);
                s1 = fmaf(a.w, cB[i].w, s1);
            }
            // reduce over the 8 k-lanes
            s0 += __shfl_xor_sync(0xffffffffu, s0, 1);
            s0 += __shfl_xor_sync(0xffffffffu, s0, 2);
            s0 += __shfl_xor_sync(0xffffffffu, s0, 4);
            s1 += __shfl_xor_sync(0xffffffffu, s1, 1);
            s1 += __shfl_xor_sync(0xffffffffu, s1, 2);
            s1 += __shfl_xor_sync(0xffffffffu, s1, 4);

            if (k == 0) {
                const float bt = __ldg(&B_stack[t * N_STATE + row]);
                const float n0 = fmaf(bt, f0, s0);
                const float n1 = fmaf(bt, f1, s1);

                cbuf[q][0][row] = n0;
                cbuf[q][1][row] = n1;

                const uint32_t off0 = (uint32_t)((q * 2 + 0) * N_STATE + row) * 4u;
                const uint32_t off1 = off0 + (uint32_t)(N_STATE * 4);
                asm volatile("st.shared::cluster.f32 [%0], %1;"
                             :: "r"(peer_base + off0), "f"(n0) : "memory");
                asm volatile("st.shared::cluster.f32 [%0], %1;"
                             :: "r"(peer_base + off1), "f"(n1) : "memory");

                cs[((size_t)(b0 + 0) * SEQLEN + t) * N_STATE + row] = n0;
                cs[((size_t)(b0 + 1) * SEQLEN + t) * N_STATE + row] = n1;
            }
        }

        asm volatile("barrier.cluster.arrive.aligned;" ::: "memory");
        asm volatile("barrier.cluster.wait.aligned;"   ::: "memory");
        p ^= 1;
    }
}

// ---------------------------------------------------------------------------
// Recon kernel: unchanged from R3 (830us) — isolates the scan delta.
// O[r, m] = sum_n X[r, n] * W[m, n]
// ---------------------------------------------------------------------------
#define RBM 128
#define RBN 128
#define RBK 16
#define RLD (RBM + 4)

__global__ void __launch_bounds__(256) hippo_recon_kernel(
    const float* __restrict__ X,   // [65536, 256]
    const float* __restrict__ W,   // [1024, 256]
    float* __restrict__ O)         // [65536, 1024]
{
    __shared__ float As[RBK][RLD];
    __shared__ float Bs[RBK][RLD];

    const int    tid  = threadIdx.x;
    const size_t row0 = (size_t)blockIdx.x * RBM;
    const int    col0 = blockIdx.y * RBN;

    const int tx  = tid & 15;
    const int ty  = tid >> 4;
    const int tm0 = ty * 8;
    const int tn0 = tx * 8;

    float acc[8][8];
    #pragma unroll
    for (int i = 0; i < 8; ++i)
        #pragma unroll
        for (int j = 0; j < 8; ++j) acc[i][j] = 0.0f;

    for (int k0 = 0; k0 < N_STATE; k0 += RBK) {
        #pragma unroll
        for (int i = 0; i < 2; ++i) {
            const int q  = tid + i * 256;
            const int r  = q >> 2;
            const int c4 = (q & 3) << 2;
            float4 v = *reinterpret_cast<const float4*>(
                X + (row0 + r) * N_STATE + k0 + c4);
            As[c4 + 0][r] = v.x;
            As[c4 + 1][r] = v.y;
            As[c4 + 2][r] = v.z;
            As[c4 + 3][r] = v.w;
            float4 w = *reinterpret_cast<const float4*>(
                W + (size_t)(col0 + r) * N_STATE + k0 + c4);
            Bs[c4 + 0][r] = w.x;
            Bs[c4 + 1][r] = w.y;
            Bs[c4 + 2][r] = w.z;
            Bs[c4 + 3][r] = w.w;
        }
        __syncthreads();

        #pragma unroll
        for (int kk = 0; kk < RBK; ++kk) {
            float4 a0 = *reinterpret_cast<const float4*>(&As[kk][tm0]);
            float4 a1 = *reinterpret_cast<const float4*>(&As[kk][tm0 + 4]);
            float4 b0 = *reinterpret_cast<const float4*>(&Bs[kk][tn0]);
            float4 b1 = *reinterpret_cast<const float4*>(&Bs[kk][tn0 + 4]);
            float am[8] = {a0.x, a0.y, a0.z, a0.w, a1.x, a1.y, a1.z, a1.w};
            float bn[8] = {b0.x, b0.y, b0.z, b0.w, b1.x, b1.y, b1.z, b1.w};
            #pragma unroll
            for (int i = 0; i < 8; ++i)
                #pragma unroll
                for (int j = 0; j < 8; ++j)
                    acc[i][j] = fmaf(am[i], bn[j], acc[i][j]);
        }
        __syncthreads();
    }

    #pragma unroll
    for (int i = 0; i < 8; ++i) {
        const size_t r = row0 + tm0 + i;
        float4 v0 = make_float4(acc[i][0], acc[i][1], acc[i][2], acc[i][3]);
        float4 v1 = make_float4(acc[i][4], acc[i][5], acc[i][6], acc[i][7]);
        *reinterpret_cast<float4*>(O + r * 1024 + col0 + tn0)     = v0;
        *reinterpret_cast<float4*>(O + r * 1024 + col0 + tn0 + 4) = v1;
    }
}

// ---------------------------------------------------------------------------
// kernel_launch
// ---------------------------------------------------------------------------
extern "C" void kernel_launch(void* const* d_in, const int* in_sizes, int n_in,
                              void* d_out, int out_size)
{
    const float* inputs   = (const float*)d_in[0];
    const float* A_stack  = (const float*)d_in[1];
    const float* B_stack  = (const float*)d_in[2];
    const float* eval_mat = (const float*)d_in[3];

    float* out   = (float*)d_out;
    float* cs    = out;                                      // 64*1024*256
    float* recon = out + (size_t)BATCH * SEQLEN * N_STATE;   // 64*1024*1024

    hippo_scan_kernel<<<BATCH, 256>>>(inputs, A_stack, B_stack, cs);

    dim3 grid((BATCH * SEQLEN) / RBM, 1024 / RBN);
    hippo_recon_kernel<<<grid, 256>>>(cs, eval_mat, recon);
}